// round 9
// baseline (speedup 1.0000x reference)
#include <cuda_runtime.h>
#include <cstdint>

#define NI 2000     // inner tree nodes
#define NL 10000    // leaves / vocab
#define ND 128      // docs
#define KC 80       // dims per dist chunk
#define KC4 (KC/4)  // 20 float4 per row
#define KC2 (KC/2)  // 40 float2 per row
#define SROW2 41    // smem row stride in float2 (odd -> conflict-free b-loads)
#define NCH_P 25    // proj chunks (2000/80)
#define NCH_M 125   // mass chunks (10000/80)
#define NCHUNK (NCH_P + NCH_M)
#define RCH 16      // argmax row chunks (125 rows each)

#define ADD_F32X2(out, a, b) \
    asm("add.rn.f32x2 %0, %1, %2;" : "=l"(out) : "l"(a), "l"(b))

// ---- scratch (static __device__, no allocation) ----
__device__ __align__(16) float g_pmax[RCH * NL];
__device__ __align__(16) int   g_pidx[RCH * NL];
__device__ __align__(16) int   g_arg[NL];
__device__ __align__(16) float g_proj[ND * NI];
__device__ __align__(16) float g_partial[NCHUNK * ND * ND];

// ---------------------------------------------------------------------------
// Kernel 1: partial column-argmax of param (2000 x 10000), float4 columns,
// 125-row chunks. grid (10, 16) x 256.
// ---------------------------------------------------------------------------
__global__ __launch_bounds__(256) void argmax_partial(const float* __restrict__ param) {
    int c4 = blockIdx.x * 256 + threadIdx.x;   // float4 column 0..2499
    if (c4 >= NL / 4) return;
    int chunk = blockIdx.y;
    int r0 = chunk * 125;
    const float4* p = (const float4*)(param + (size_t)r0 * NL) + c4;
    float4 m = p[0];
    int4 mi = make_int4(r0, r0, r0, r0);
#pragma unroll 5
    for (int r = 1; r < 125; r++) {
        float4 v = p[(size_t)r * (NL / 4)];
        if (v.x > m.x) { m.x = v.x; mi.x = r0 + r; }
        if (v.y > m.y) { m.y = v.y; mi.y = r0 + r; }
        if (v.z > m.z) { m.z = v.z; mi.z = r0 + r; }
        if (v.w > m.w) { m.w = v.w; mi.w = r0 + r; }
    }
    ((float4*)g_pmax)[chunk * (NL / 4) + c4] = m;
    ((int4*)g_pidx)[chunk * (NL / 4) + c4] = mi;
}

__global__ __launch_bounds__(256) void argmax_reduce() {
    int c4 = blockIdx.x * 256 + threadIdx.x;
    if (c4 >= NL / 4) return;
    float4 m = ((float4*)g_pmax)[c4];
    int4 mi = ((int4*)g_pidx)[c4];
#pragma unroll
    for (int c = 1; c < RCH; c++) {
        float4 v = ((float4*)g_pmax)[c * (NL / 4) + c4];
        int4 vi = ((int4*)g_pidx)[c * (NL / 4) + c4];
        if (v.x > m.x) { m.x = v.x; mi.x = vi.x; }
        if (v.y > m.y) { m.y = v.y; mi.y = vi.y; }
        if (v.z > m.z) { m.z = v.z; mi.z = vi.z; }
        if (v.w > m.w) { m.w = v.w; mi.w = vi.w; }
    }
    ((int4*)g_arg)[c4] = mi;
}

// ---------------------------------------------------------------------------
// Kernel 2: per-doc node-mass scatter + bottom-up subtree sums -> proj.
// ---------------------------------------------------------------------------
__global__ __launch_bounds__(256) void proj_kernel(const float* __restrict__ mass) {
    __shared__ float s[NI];
    int d = blockIdx.x;
    int tid = threadIdx.x;
    for (int i = tid; i < NI; i += 256) s[i] = 0.f;
    __syncthreads();

    const float* mrow = mass + (size_t)d * NL;
    for (int l = tid; l < NL; l += 256)
        atomicAdd(&s[g_arg[l]], mrow[l]);
    __syncthreads();

    const int lo[5] = {156, 31, 6, 1, 0};
    const int hi[5] = {399, 155, 30, 5, 0};
#pragma unroll
    for (int ph = 0; ph < 5; ph++) {
        for (int r = lo[ph] + tid; r <= hi[ph]; r += 256) {
            int c0 = 5 * r + 1;
            float acc = s[r] + s[c0] + s[c0 + 1] + s[c0 + 2] + s[c0 + 3];
            if (c0 + 4 < NI) acc += s[c0 + 4];   // node 399 has 4 children
            s[r] = acc;
        }
        __syncthreads();
    }
    for (int i = tid; i < NI; i += 256)
        g_proj[(size_t)d * NI + i] = s[i];
}

// ---------------------------------------------------------------------------
// Kernel 3: pairwise L1 partials. 64x64 tiles (3 upper), KC=80 dim chunks.
// 256 threads, 4x4 register blocking, packed f32x2 math:
//   shQ holds NEGATED q-rows  ->  |a - b| = abs_f32x2(add.f32x2(a, qneg))
//   1 fma-pipe + 1 alu-pipe instr per element (2x scalar FADD rate).
// ---------------------------------------------------------------------------
__global__ __launch_bounds__(256) void dist_kernel(const float* __restrict__ gsrc,
                                                   int stride, int chunkBase,
                                                   int useProj) {
    __shared__ __align__(16) float2 shP[64 * SROW2];
    __shared__ __align__(16) float2 shQ[64 * SROW2];

    const float* src = useProj ? g_proj : gsrc;

    int tile  = blockIdx.x;   // 0:(0,0) 1:(0,1) 2:(1,1)
    int chunk = blockIdx.y;
    int tp = (tile == 2) ? 1 : 0;
    int tq = (tile == 0) ? 0 : 1;
    int p0 = tp * 64, q0 = tq * 64;
    int d0 = chunk * KC;

    int tid = threadIdx.x;
    int tx = tid & 15, ty = tid >> 4;

    // stage: 64 rows x 20 float4 each for P (positive) and Q (negated)
    for (int i4 = tid; i4 < 64 * KC4; i4 += 256) {
        int row = i4 / KC4, k4 = i4 % KC4;
        const float4* gp = (const float4*)(src + (size_t)(p0 + row) * stride + d0);
        const float4* gq = (const float4*)(src + (size_t)(q0 + row) * stride + d0);
        float4 vp = gp[k4];
        float4 vq = gq[k4];
        shP[row * SROW2 + 2 * k4    ] = make_float2(vp.x, vp.y);
        shP[row * SROW2 + 2 * k4 + 1] = make_float2(vp.z, vp.w);
        shQ[row * SROW2 + 2 * k4    ] = make_float2(-vq.x, -vq.y);
        shQ[row * SROW2 + 2 * k4 + 1] = make_float2(-vq.z, -vq.w);
    }
    __syncthreads();

    const uint64_t* sp8 = (const uint64_t*)shP;
    const uint64_t* sq8 = (const uint64_t*)shQ;
    const uint64_t ABSM = 0x7FFFFFFF7FFFFFFFull;

    uint64_t acc2[4][4] = {};
#pragma unroll 2
    for (int k2 = 0; k2 < KC2; k2++) {
        uint64_t a2[4], b2[4];
#pragma unroll
        for (int i = 0; i < 4; i++) a2[i] = sp8[(ty + 16 * i) * SROW2 + k2];
#pragma unroll
        for (int j = 0; j < 4; j++) b2[j] = sq8[(tx + 16 * j) * SROW2 + k2];
#pragma unroll
        for (int i = 0; i < 4; i++)
#pragma unroll
            for (int j = 0; j < 4; j++) {
                uint64_t d;
                ADD_F32X2(d, a2[i], b2[j]);   // a - b (b pre-negated)
                d &= ABSM;                    // packed |.| (2x LOP3, alu pipe)
                ADD_F32X2(acc2[i][j], acc2[i][j], d);
            }
    }

    float* part = g_partial + (size_t)(chunkBase + chunk) * ND * ND;
#pragma unroll
    for (int i = 0; i < 4; i++) {
        int p = p0 + ty + 16 * i;
#pragma unroll
        for (int j = 0; j < 4; j++) {
            int q = q0 + tx + 16 * j;
            float flo = __uint_as_float((unsigned)(acc2[i][j] & 0xFFFFFFFFu));
            float fhi = __uint_as_float((unsigned)(acc2[i][j] >> 32));
            part[p * ND + q] = flo + fhi;
        }
    }
}

// ---------------------------------------------------------------------------
// Kernel 4: reduce partials, mirror lower triangle.
// ---------------------------------------------------------------------------
__global__ __launch_bounds__(256) void reduce_kernel(float* __restrict__ out) {
    int idx = blockIdx.x * 256 + threadIdx.x;
    if (idx >= ND * ND) return;
    int p = idx / ND, q = idx % ND;
    int sp = p, sq = q;
    if ((p >> 6) > (q >> 6)) { sp = q; sq = p; }  // mirror lower tile
    float s = 0.f;
#pragma unroll 10
    for (int c = 0; c < NCHUNK; c++)
        s += g_partial[c * ND * ND + sp * ND + sq];
    out[idx] = s;
}

// ---------------------------------------------------------------------------
extern "C" void kernel_launch(void* const* d_in, const int* in_sizes, int n_in,
                              void* d_out, int out_size) {
    const float* mass  = (const float*)d_in[0];
    const float* param = (const float*)d_in[1];
    if (n_in >= 2 && in_sizes[0] == NI * NL) {   // robust to input ordering
        param = (const float*)d_in[0];
        mass  = (const float*)d_in[1];
    }

    // lazy side-stream for fork/join overlap (created on the uncaptured
    // correctness call; only record/wait ops appear during capture)
    static cudaStream_t sB = nullptr;
    static cudaEvent_t evFork = nullptr, evJoin = nullptr;
    static int initTried = 0;
    if (!initTried) {
        initTried = 1;
        if (cudaStreamCreateWithFlags(&sB, cudaStreamNonBlocking) != cudaSuccess) sB = nullptr;
        if (sB) {
            if (cudaEventCreateWithFlags(&evFork, cudaEventDisableTiming) != cudaSuccess ||
                cudaEventCreateWithFlags(&evJoin, cudaEventDisableTiming) != cudaSuccess) {
                sB = nullptr;
            }
        }
    }

    if (sB) {
        // fork: mass-part dist chunks are independent of argmax/proj
        cudaEventRecord(evFork, 0);
        cudaStreamWaitEvent(sB, evFork, 0);
        dist_kernel<<<dim3(3, NCH_M), 256, 0, sB>>>(mass, NL, NCH_P, 0);

        argmax_partial<<<dim3(10, RCH), 256>>>(param);
        argmax_reduce<<<10, 256>>>();
        proj_kernel<<<ND, 256>>>(mass);
        dist_kernel<<<dim3(3, NCH_P), 256>>>(nullptr, NI, 0, 1);

        cudaEventRecord(evJoin, sB);
        cudaStreamWaitEvent(0, evJoin, 0);
    } else {
        // sequential fallback
        dist_kernel<<<dim3(3, NCH_M), 256>>>(mass, NL, NCH_P, 0);
        argmax_partial<<<dim3(10, RCH), 256>>>(param);
        argmax_reduce<<<10, 256>>>();
        proj_kernel<<<ND, 256>>>(mass);
        dist_kernel<<<dim3(3, NCH_P), 256>>>(nullptr, NI, 0, 1);
    }

    reduce_kernel<<<(ND * ND + 255) / 256, 256>>>((float*)d_out);
}

// round 10
// speedup vs baseline: 1.5616x; 1.5616x over previous
#include <cuda_runtime.h>
#include <cstdint>

#define NI 2000     // inner tree nodes
#define NL 10000    // leaves / vocab
#define ND 128      // docs
#define KC 80       // dims per dist chunk
#define KC4 (KC/4)  // 20 float4 per row
#define KC2 (KC/2)  // 40 float2 per row
#define SROW2 41    // smem row stride in float2 (odd -> conflict-free b-loads)
#define NCH_P 25    // proj chunks (2000/80)
#define NCH_M 125   // mass chunks (10000/80)
#define NCHUNK (NCH_P + NCH_M)
#define RCH 16      // argmax row chunks (125 rows each)
#define PPARTS 4    // leaf partitions per doc for proj scatter
#define PLEAF (NL/PPARTS)   // 2500 leaves per partition

#define ADD_F32X2(out, a, b) \
    asm("add.rn.f32x2 %0, %1, %2;" : "=l"(out) : "l"(a), "l"(b))

// ---- scratch (static __device__, no allocation) ----
__device__ __align__(16) float g_pmax[RCH * NL];
__device__ __align__(16) int   g_pidx[RCH * NL];
__device__ __align__(16) int   g_arg[NL];
__device__ __align__(16) float g_psum[PPARTS * ND * NI];
__device__ __align__(16) float g_proj[ND * NI];
__device__ __align__(16) float g_partial[NCHUNK * ND * ND];

// ---------------------------------------------------------------------------
// Kernel 1: partial column-argmax of param (2000 x 10000), float4 columns.
// ---------------------------------------------------------------------------
__global__ __launch_bounds__(256) void argmax_partial(const float* __restrict__ param) {
    int c4 = blockIdx.x * 256 + threadIdx.x;   // float4 column 0..2499
    if (c4 >= NL / 4) return;
    int chunk = blockIdx.y;
    int r0 = chunk * 125;
    const float4* p = (const float4*)(param + (size_t)r0 * NL) + c4;
    float4 m = p[0];
    int4 mi = make_int4(r0, r0, r0, r0);
#pragma unroll 4
    for (int r = 1; r < 125; r++) {
        float4 v = p[(size_t)r * (NL / 4)];
        if (v.x > m.x) { m.x = v.x; mi.x = r0 + r; }
        if (v.y > m.y) { m.y = v.y; mi.y = r0 + r; }
        if (v.z > m.z) { m.z = v.z; mi.z = r0 + r; }
        if (v.w > m.w) { m.w = v.w; mi.w = r0 + r; }
    }
    ((float4*)g_pmax)[chunk * (NL / 4) + c4] = m;
    ((int4*)g_pidx)[chunk * (NL / 4) + c4] = mi;
}

__global__ __launch_bounds__(256) void argmax_reduce() {
    int c4 = blockIdx.x * 256 + threadIdx.x;
    if (c4 >= NL / 4) return;
    float4 m = ((float4*)g_pmax)[c4];
    int4 mi = ((int4*)g_pidx)[c4];
#pragma unroll
    for (int c = 1; c < RCH; c++) {
        float4 v = ((float4*)g_pmax)[c * (NL / 4) + c4];
        int4 vi = ((int4*)g_pidx)[c * (NL / 4) + c4];
        if (v.x > m.x) { m.x = v.x; mi.x = vi.x; }
        if (v.y > m.y) { m.y = v.y; mi.y = vi.y; }
        if (v.z > m.z) { m.z = v.z; mi.z = vi.z; }
        if (v.w > m.w) { m.w = v.w; mi.w = vi.w; }
    }
    ((int4*)g_arg)[c4] = mi;
}

// ---------------------------------------------------------------------------
// Kernel 2a: partial node-mass scatter. grid (ND, PPARTS).
// Each CTA handles 2500 leaves of one doc: batched loads (MLP=10) then
// smem atomics (4x fewer atomics per SM than one-CTA-per-doc).
// ---------------------------------------------------------------------------
__global__ __launch_bounds__(256) void proj_partial(const float* __restrict__ mass) {
    __shared__ float s[NI];
    int d = blockIdx.x;
    int part = blockIdx.y;
    int tid = threadIdx.x;
    for (int i = tid; i < NI; i += 256) s[i] = 0.f;
    __syncthreads();

    const float* mrow = mass + (size_t)d * NL + part * PLEAF;
    const int*   arow = g_arg + part * PLEAF;

    float v[10];
    int   a[10];
#pragma unroll
    for (int it = 0; it < 10; it++) {        // independent loads first (MLP)
        int l = tid + it * 256;
        if (l < PLEAF) { v[it] = mrow[l]; a[it] = arow[l]; }
    }
#pragma unroll
    for (int it = 0; it < 10; it++) {
        int l = tid + it * 256;
        if (l < PLEAF) atomicAdd(&s[a[it]], v[it]);
    }
    __syncthreads();

    float* out = g_psum + ((size_t)part * ND + d) * NI;
    for (int i = tid; i < NI; i += 256) out[i] = s[i];
}

// ---------------------------------------------------------------------------
// Kernel 2b: merge 4 partials + bottom-up tree sum -> proj. grid ND.
// ---------------------------------------------------------------------------
__global__ __launch_bounds__(256) void proj_tree() {
    __shared__ float s[NI];
    int d = blockIdx.x;
    int tid = threadIdx.x;

    const float4* p0 = (const float4*)(g_psum + ((size_t)0 * ND + d) * NI);
    const float4* p1 = (const float4*)(g_psum + ((size_t)1 * ND + d) * NI);
    const float4* p2 = (const float4*)(g_psum + ((size_t)2 * ND + d) * NI);
    const float4* p3 = (const float4*)(g_psum + ((size_t)3 * ND + d) * NI);
    for (int i4 = tid; i4 < NI / 4; i4 += 256) {
        float4 a = p0[i4], b = p1[i4], c = p2[i4], e = p3[i4];
        ((float4*)s)[i4] = make_float4(a.x + b.x + c.x + e.x,
                                       a.y + b.y + c.y + e.y,
                                       a.z + b.z + c.z + e.z,
                                       a.w + b.w + c.w + e.w);
    }
    __syncthreads();

    const int lo[5] = {156, 31, 6, 1, 0};
    const int hi[5] = {399, 155, 30, 5, 0};
#pragma unroll
    for (int ph = 0; ph < 5; ph++) {
        for (int r = lo[ph] + tid; r <= hi[ph]; r += 256) {
            int c0 = 5 * r + 1;
            float acc = s[r] + s[c0] + s[c0 + 1] + s[c0 + 2] + s[c0 + 3];
            if (c0 + 4 < NI) acc += s[c0 + 4];   // node 399 has 4 children
            s[r] = acc;
        }
        __syncthreads();
    }
    for (int i = tid; i < NI; i += 256)
        g_proj[(size_t)d * NI + i] = s[i];
}

// ---------------------------------------------------------------------------
// Kernel 3: pairwise L1 partials. 64x64 tiles (3 upper), KC=80 dim chunks.
// 256 threads, 4x4 register blocking, packed f32x2 math:
//   shQ holds NEGATED q-rows  ->  |a - b| = abs_f32x2(add.f32x2(a, qneg))
// ---------------------------------------------------------------------------
__global__ __launch_bounds__(256) void dist_kernel(const float* __restrict__ gsrc,
                                                   int stride, int chunkBase,
                                                   int useProj) {
    __shared__ __align__(16) float2 shP[64 * SROW2];
    __shared__ __align__(16) float2 shQ[64 * SROW2];

    const float* src = useProj ? g_proj : gsrc;

    int tile  = blockIdx.x;   // 0:(0,0) 1:(0,1) 2:(1,1)
    int chunk = blockIdx.y;
    int tp = (tile == 2) ? 1 : 0;
    int tq = (tile == 0) ? 0 : 1;
    int p0 = tp * 64, q0 = tq * 64;
    int d0 = chunk * KC;

    int tid = threadIdx.x;
    int tx = tid & 15, ty = tid >> 4;

    for (int i4 = tid; i4 < 64 * KC4; i4 += 256) {
        int row = i4 / KC4, k4 = i4 % KC4;
        const float4* gp = (const float4*)(src + (size_t)(p0 + row) * stride + d0);
        const float4* gq = (const float4*)(src + (size_t)(q0 + row) * stride + d0);
        float4 vp = gp[k4];
        float4 vq = gq[k4];
        shP[row * SROW2 + 2 * k4    ] = make_float2(vp.x, vp.y);
        shP[row * SROW2 + 2 * k4 + 1] = make_float2(vp.z, vp.w);
        shQ[row * SROW2 + 2 * k4    ] = make_float2(-vq.x, -vq.y);
        shQ[row * SROW2 + 2 * k4 + 1] = make_float2(-vq.z, -vq.w);
    }
    __syncthreads();

    const uint64_t* sp8 = (const uint64_t*)shP;
    const uint64_t* sq8 = (const uint64_t*)shQ;
    const uint64_t ABSM = 0x7FFFFFFF7FFFFFFFull;

    uint64_t acc2[4][4] = {};
#pragma unroll 2
    for (int k2 = 0; k2 < KC2; k2++) {
        uint64_t a2[4], b2[4];
#pragma unroll
        for (int i = 0; i < 4; i++) a2[i] = sp8[(ty + 16 * i) * SROW2 + k2];
#pragma unroll
        for (int j = 0; j < 4; j++) b2[j] = sq8[(tx + 16 * j) * SROW2 + k2];
#pragma unroll
        for (int i = 0; i < 4; i++)
#pragma unroll
            for (int j = 0; j < 4; j++) {
                uint64_t d;
                ADD_F32X2(d, a2[i], b2[j]);   // a - b (b pre-negated)
                d &= ABSM;                    // packed |.| (alu pipe)
                ADD_F32X2(acc2[i][j], acc2[i][j], d);
            }
    }

    float* part = g_partial + (size_t)(chunkBase + chunk) * ND * ND;
#pragma unroll
    for (int i = 0; i < 4; i++) {
        int p = p0 + ty + 16 * i;
#pragma unroll
        for (int j = 0; j < 4; j++) {
            int q = q0 + tx + 16 * j;
            float flo = __uint_as_float((unsigned)(acc2[i][j] & 0xFFFFFFFFu));
            float fhi = __uint_as_float((unsigned)(acc2[i][j] >> 32));
            part[p * ND + q] = flo + fhi;
        }
    }
}

// ---------------------------------------------------------------------------
// Kernel 4: reduce partials, mirror lower triangle.
// ---------------------------------------------------------------------------
__global__ __launch_bounds__(256) void reduce_kernel(float* __restrict__ out) {
    int idx = blockIdx.x * 256 + threadIdx.x;
    if (idx >= ND * ND) return;
    int p = idx / ND, q = idx % ND;
    int sp = p, sq = q;
    if ((p >> 6) > (q >> 6)) { sp = q; sq = p; }  // mirror lower tile
    float s = 0.f;
#pragma unroll 10
    for (int c = 0; c < NCHUNK; c++)
        s += g_partial[c * ND * ND + sp * ND + sq];
    out[idx] = s;
}

// ---------------------------------------------------------------------------
extern "C" void kernel_launch(void* const* d_in, const int* in_sizes, int n_in,
                              void* d_out, int out_size) {
    const float* mass  = (const float*)d_in[0];
    const float* param = (const float*)d_in[1];
    if (n_in >= 2 && in_sizes[0] == NI * NL) {   // robust to input ordering
        param = (const float*)d_in[0];
        mass  = (const float*)d_in[1];
    }

    // fully sequential, single stream (R9 showed dual-stream contention
    // inflates the latency-critical chain during timed replay)
    argmax_partial<<<dim3(10, RCH), 256>>>(param);
    argmax_reduce<<<10, 256>>>();
    proj_partial<<<dim3(ND, PPARTS), 256>>>(mass);
    proj_tree<<<ND, 256>>>();
    dist_kernel<<<dim3(3, NCH_M), 256>>>(mass, NL, NCH_P, 0);
    dist_kernel<<<dim3(3, NCH_P), 256>>>(nullptr, NI, 0, 1);
    reduce_kernel<<<(ND * ND + 255) / 256, 256>>>((float*)d_out);
}

// round 11
// speedup vs baseline: 2.6503x; 1.6971x over previous
#include <cuda_runtime.h>
#include <cstdint>

#define NI 2000     // inner tree nodes
#define NL 10000    // leaves / vocab
#define ND 128      // docs
#define KC 80       // dims per dist chunk
#define KC4 (KC/4)  // 20 float4 per row
#define KC2 (KC/2)  // 40 float2 per row
#define SROW2 41    // smem row stride in float2 (odd -> conflict-free b-loads)
#define NCH_P 25    // proj chunks (2000/80)
#define NCH_M 125   // mass chunks (10000/80)
#define NCHUNK (NCH_P + NCH_M)
#define RCH 16      // argmax row chunks (125 rows each)
#define PPARTS 4    // leaf partitions per doc for proj scatter
#define PLEAF (NL/PPARTS)   // 2500 leaves per partition

#define ADD_F32X2(out, a, b) \
    asm("add.rn.f32x2 %0, %1, %2;" : "=l"(out) : "l"(a), "l"(b))

// ---- scratch (static __device__, no allocation) ----
__device__ __align__(16) float g_pmax[RCH * NL];
__device__ __align__(16) int   g_pidx[RCH * NL];
__device__ __align__(16) int   g_arg[NL];
__device__ __align__(16) float g_proj[ND * NI];

// ---------------------------------------------------------------------------
// Kernel 1: partial column-argmax of param (2000 x 10000), float4 columns.
// Also zeroes d_out and g_proj (needed by the atomic-accumulate kernels).
// grid (10, 16) x 256.
// ---------------------------------------------------------------------------
__global__ __launch_bounds__(256) void argmax_partial(const float* __restrict__ param,
                                                      float* __restrict__ out) {
    int bid = blockIdx.y * 10 + blockIdx.x;          // 0..159
    int gtid = bid * 256 + threadIdx.x;              // 0..40959
    if (gtid < ND * ND) out[gtid] = 0.f;             // zero d_out (16384)
    for (int i = gtid; i < ND * NI; i += 160 * 256)  // zero g_proj (256000)
        g_proj[i] = 0.f;

    int c4 = blockIdx.x * 256 + threadIdx.x;   // float4 column 0..2499
    if (c4 >= NL / 4) return;
    int chunk = blockIdx.y;
    int r0 = chunk * 125;
    const float4* p = (const float4*)(param + (size_t)r0 * NL) + c4;
    float4 m = p[0];
    int4 mi = make_int4(r0, r0, r0, r0);
#pragma unroll 4
    for (int r = 1; r < 125; r++) {
        float4 v = p[(size_t)r * (NL / 4)];
        if (v.x > m.x) { m.x = v.x; mi.x = r0 + r; }
        if (v.y > m.y) { m.y = v.y; mi.y = r0 + r; }
        if (v.z > m.z) { m.z = v.z; mi.z = r0 + r; }
        if (v.w > m.w) { m.w = v.w; mi.w = r0 + r; }
    }
    ((float4*)g_pmax)[chunk * (NL / 4) + c4] = m;
    ((int4*)g_pidx)[chunk * (NL / 4) + c4] = mi;
}

__global__ __launch_bounds__(256) void argmax_reduce() {
    int c4 = blockIdx.x * 256 + threadIdx.x;
    if (c4 >= NL / 4) return;
    float4 m = ((float4*)g_pmax)[c4];
    int4 mi = ((int4*)g_pidx)[c4];
#pragma unroll
    for (int c = 1; c < RCH; c++) {
        float4 v = ((float4*)g_pmax)[c * (NL / 4) + c4];
        int4 vi = ((int4*)g_pidx)[c * (NL / 4) + c4];
        if (v.x > m.x) { m.x = v.x; mi.x = vi.x; }
        if (v.y > m.y) { m.y = v.y; mi.y = vi.y; }
        if (v.z > m.z) { m.z = v.z; mi.z = vi.z; }
        if (v.w > m.w) { m.w = v.w; mi.w = vi.w; }
    }
    ((int4*)g_arg)[c4] = mi;
}

// ---------------------------------------------------------------------------
// Kernel 2: scatter + tree-sum + atomic merge. grid (ND, PPARTS).
// Tree sum is LINEAR, so each CTA tree-sums its own partial scatter and
// atomically merges into g_proj — no separate merge kernel needed.
// ---------------------------------------------------------------------------
__global__ __launch_bounds__(256) void proj_scatter_tree(const float* __restrict__ mass) {
    __shared__ float s[NI];
    int d = blockIdx.x;
    int part = blockIdx.y;
    int tid = threadIdx.x;
    for (int i = tid; i < NI; i += 256) s[i] = 0.f;
    __syncthreads();

    const float* mrow = mass + (size_t)d * NL + part * PLEAF;
    const int*   arow = g_arg + part * PLEAF;

    float v[10];
    int   a[10];
#pragma unroll
    for (int it = 0; it < 10; it++) {        // independent loads first (MLP)
        int l = tid + it * 256;
        if (l < PLEAF) { v[it] = mrow[l]; a[it] = arow[l]; }
    }
#pragma unroll
    for (int it = 0; it < 10; it++) {
        int l = tid + it * 256;
        if (l < PLEAF) atomicAdd(&s[a[it]], v[it]);
    }
    __syncthreads();

    const int lo[5] = {156, 31, 6, 1, 0};
    const int hi[5] = {399, 155, 30, 5, 0};
#pragma unroll
    for (int ph = 0; ph < 5; ph++) {
        for (int r = lo[ph] + tid; r <= hi[ph]; r += 256) {
            int c0 = 5 * r + 1;
            float acc = s[r] + s[c0] + s[c0 + 1] + s[c0 + 2] + s[c0 + 3];
            if (c0 + 4 < NI) acc += s[c0 + 4];   // node 399 has 4 children
            s[r] = acc;
        }
        __syncthreads();
    }
    float* dst = g_proj + (size_t)d * NI;
    for (int i = tid; i < NI; i += 256)
        atomicAdd(&dst[i], s[i]);
}

// ---------------------------------------------------------------------------
// Kernel 3: fused pairwise L1. grid (3, 150): chunks 0..24 over proj,
// 25..149 over mass. Accumulates directly into out via atomics (+mirror).
// Packed f32x2 math: shQ negated -> |a-b| = and_mask(add.f32x2(a, qneg)).
// ---------------------------------------------------------------------------
__global__ __launch_bounds__(256) void dist_fused(const float* __restrict__ mass,
                                                  float* __restrict__ out) {
    __shared__ __align__(16) float2 shP[64 * SROW2];
    __shared__ __align__(16) float2 shQ[64 * SROW2];

    int tile  = blockIdx.x;   // 0:(0,0) 1:(0,1) 2:(1,1)
    int chunk = blockIdx.y;   // 0..149

    const float* src;
    int stride, d0;
    if (chunk < NCH_P) { src = g_proj; stride = NI; d0 = chunk * KC; }
    else               { src = mass;   stride = NL; d0 = (chunk - NCH_P) * KC; }

    int tp = (tile == 2) ? 1 : 0;
    int tq = (tile == 0) ? 0 : 1;
    int p0 = tp * 64, q0 = tq * 64;

    int tid = threadIdx.x;
    int tx = tid & 15, ty = tid >> 4;

    for (int i4 = tid; i4 < 64 * KC4; i4 += 256) {
        int row = i4 / KC4, k4 = i4 % KC4;
        const float4* gp = (const float4*)(src + (size_t)(p0 + row) * stride + d0);
        const float4* gq = (const float4*)(src + (size_t)(q0 + row) * stride + d0);
        float4 vp = gp[k4];
        float4 vq = gq[k4];
        shP[row * SROW2 + 2 * k4    ] = make_float2(vp.x, vp.y);
        shP[row * SROW2 + 2 * k4 + 1] = make_float2(vp.z, vp.w);
        shQ[row * SROW2 + 2 * k4    ] = make_float2(-vq.x, -vq.y);
        shQ[row * SROW2 + 2 * k4 + 1] = make_float2(-vq.z, -vq.w);
    }
    __syncthreads();

    const uint64_t* sp8 = (const uint64_t*)shP;
    const uint64_t* sq8 = (const uint64_t*)shQ;
    const uint64_t ABSM = 0x7FFFFFFF7FFFFFFFull;

    uint64_t acc2[4][4] = {};
#pragma unroll 2
    for (int k2 = 0; k2 < KC2; k2++) {
        uint64_t a2[4], b2[4];
#pragma unroll
        for (int i = 0; i < 4; i++) a2[i] = sp8[(ty + 16 * i) * SROW2 + k2];
#pragma unroll
        for (int j = 0; j < 4; j++) b2[j] = sq8[(tx + 16 * j) * SROW2 + k2];
#pragma unroll
        for (int i = 0; i < 4; i++)
#pragma unroll
            for (int j = 0; j < 4; j++) {
                uint64_t d;
                ADD_F32X2(d, a2[i], b2[j]);   // a - b (b pre-negated)
                d &= ABSM;                    // packed |.| (alu pipe)
                ADD_F32X2(acc2[i][j], acc2[i][j], d);
            }
    }

#pragma unroll
    for (int i = 0; i < 4; i++) {
        int p = p0 + ty + 16 * i;
#pragma unroll
        for (int j = 0; j < 4; j++) {
            int q = q0 + tx + 16 * j;
            float flo = __uint_as_float((unsigned)(acc2[i][j] & 0xFFFFFFFFu));
            float fhi = __uint_as_float((unsigned)(acc2[i][j] >> 32));
            float v = flo + fhi;
            atomicAdd(&out[p * ND + q], v);
            if (tile == 1) atomicAdd(&out[q * ND + p], v);   // mirror
        }
    }
}

// ---------------------------------------------------------------------------
extern "C" void kernel_launch(void* const* d_in, const int* in_sizes, int n_in,
                              void* d_out, int out_size) {
    const float* mass  = (const float*)d_in[0];
    const float* param = (const float*)d_in[1];
    if (n_in >= 2 && in_sizes[0] == NI * NL) {   // robust to input ordering
        param = (const float*)d_in[0];
        mass  = (const float*)d_in[1];
    }
    float* out = (float*)d_out;

    argmax_partial<<<dim3(10, RCH), 256>>>(param, out);  // + zero out/g_proj
    argmax_reduce<<<10, 256>>>();
    proj_scatter_tree<<<dim3(ND, PPARTS), 256>>>(mass);
    dist_fused<<<dim3(3, NCHUNK), 256>>>(mass, out);
}